// round 2
// baseline (speedup 1.0000x reference)
#include <cuda_runtime.h>
#include <math.h>

// Problem constants
#define BB   64
#define SS   256
#define INF  512
#define HH   1024
#define OO   512
#define KTCK 4
#define TT   (SS*KTCK)   // 1024 total ticks

// Static device scratch (no runtime allocation allowed)
__device__ float g_gi[(size_t)SS*BB*3*HH];    // [s][b][3H] precomputed input gates
__device__ float g_hist[(size_t)TT*BB*HH];    // [t][b][H] hidden state history
__device__ float g_h0[(size_t)BB*HH];         // zero-init, never written: h(-1)=0
__device__ unsigned int g_barr[TT];           // per-tick grid-barrier slots (memset each launch)

// Packed fp32x2 FMA (sm_100a packed-fp32 path: 2 FMAs per instruction, full fp32)
__device__ __forceinline__ void fma2(unsigned long long &acc,
                                     unsigned long long a,
                                     unsigned long long b)
{
    asm volatile("fma.rn.f32x2 %0, %1, %2, %0;" : "+l"(acc) : "l"(a), "l"(b));
}
__device__ __forceinline__ float fold2(unsigned long long a)
{
    float lo = __uint_as_float((unsigned)(a & 0xffffffffull));
    float hi = __uint_as_float((unsigned)(a >> 32));
    return lo + hi;
}

// ---------------------------------------------------------------------------
// K1: gi[s][b][:] = x[b][s][:] @ W_ih^T + b_ih   (fp32 tiled GEMM, 128x128)
// ---------------------------------------------------------------------------
__global__ __launch_bounds__(256) void gi_kernel(const float* __restrict__ x,
                                                 const float* __restrict__ Wih,
                                                 const float* __restrict__ bih)
{
    __shared__ float As[8][128];
    __shared__ float Bs[8][128];
    const int mbase = blockIdx.y * 128;
    const int nbase = blockIdx.x * 128;
    const int tid   = threadIdx.x;
    const int lrow  = tid >> 1;
    const int lkq   = (tid & 1) * 4;
    const int tx    = (tid & 15) * 8;
    const int ty    = (tid >> 4) * 8;

    float acc[8][8];
#pragma unroll
    for (int i = 0; i < 8; i++)
#pragma unroll
        for (int j = 0; j < 8; j++) acc[i][j] = 0.f;

    for (int k0 = 0; k0 < INF; k0 += 8) {
        float4 av = *(const float4*)&x[(size_t)(mbase + lrow) * INF + k0 + lkq];
        float4 bv = *(const float4*)&Wih[(size_t)(nbase + lrow) * INF + k0 + lkq];
        __syncthreads();
        As[lkq + 0][lrow] = av.x; As[lkq + 1][lrow] = av.y;
        As[lkq + 2][lrow] = av.z; As[lkq + 3][lrow] = av.w;
        Bs[lkq + 0][lrow] = bv.x; Bs[lkq + 1][lrow] = bv.y;
        Bs[lkq + 2][lrow] = bv.z; Bs[lkq + 3][lrow] = bv.w;
        __syncthreads();
#pragma unroll
        for (int kk = 0; kk < 8; kk++) {
            float ar[8], br[8];
#pragma unroll
            for (int i = 0; i < 8; i++) ar[i] = As[kk][ty + i];
#pragma unroll
            for (int j = 0; j < 8; j++) br[j] = Bs[kk][tx + j];
#pragma unroll
            for (int i = 0; i < 8; i++)
#pragma unroll
                for (int j = 0; j < 8; j++) acc[i][j] += ar[i] * br[j];
        }
    }

#pragma unroll
    for (int i = 0; i < 8; i++) {
        int m = mbase + ty + i;
        int b = m >> 8;          // m = b*256 + s
        int s = m & 255;
        size_t rowo = ((size_t)(s * BB + b)) * (3 * HH);
#pragma unroll
        for (int j = 0; j < 8; j++) {
            int n = nbase + tx + j;
            g_gi[rowo + n] = acc[i][j] + bih[n];
        }
    }
}

// ---------------------------------------------------------------------------
// K2: PERSISTENT recurrence kernel. 128 blocks (1/SM) x 256 threads.
// Block owns hidden units [jbase, jbase+8) -> 24 W_hh rows kept in SMEM for
// the whole kernel. Per tick: stage h in 4 chunks of 256 k, 8 warps split K,
// per-thread 8b x 2j x 3g tile with packed f32x2 FMAs, cross-warp smem
// reduction (reusing the h-staging buffer), fused gate epilogue, then a
// device-wide barrier on g_barr[t].
// ---------------------------------------------------------------------------
#define WS_STRIDE 1036
#define HS_STRIDE 260
#define REC_SMEM ((24*WS_STRIDE + 64*HS_STRIDE) * 4)   // ~166 KB

__global__ __launch_bounds__(256, 1) void rec_kernel(const float* __restrict__ Whh,
                                                     const float* __restrict__ bhh)
{
    extern __shared__ float smem[];
    float* ws  = smem;                  // [24][WS_STRIDE]  W_hh slice, whole K
    float* hs  = smem + 24 * WS_STRIDE; // [64][HS_STRIDE]  h chunk, reused as red
    float* red = hs;                    // [8][1536] cross-warp partials

    const int tid   = threadIdx.x;
    const int w     = tid >> 5;
    const int lane  = tid & 31;
    const int jbase = blockIdx.x * 8;
    const int bg = lane & 7;   // b = bg + 8*i
    const int jp = lane >> 3;  // j_local = jp*2 + jj

    // One-time: load this block's 24 W_hh rows into SMEM
#pragma unroll 1
    for (int i = 0; i < 24; i++) {
        int idx = i * 256 + tid;        // [0, 6144)
        int r   = idx >> 8;             // row 0..23
        int kq  = (idx & 255) * 4;
        int g   = r >> 3;
        int jl  = r & 7;
        float4 wv = *(const float4*)&Whh[(size_t)(g * HH + jbase + jl) * HH + kq];
        *(float4*)&ws[r * WS_STRIDE + kq] = wv;
    }
    __syncthreads();

#pragma unroll 1
    for (int t = 0; t < TT; t++) {
        const int s = t >> 2;
        const float* __restrict__ hprev =
            (t == 0) ? g_h0 : (g_hist + (size_t)(t - 1) * BB * HH);

        unsigned long long acc2[8][2][3];
#pragma unroll
        for (int i = 0; i < 8; i++)
#pragma unroll
            for (int jj = 0; jj < 2; jj++)
#pragma unroll
                for (int g = 0; g < 3; g++) acc2[i][jj][g] = 0ull;

#pragma unroll 1
        for (int p = 0; p < 4; p++) {
            const int kb = p * 256;
            __syncthreads();   // hs free (prev phase compute / prev tick red done)
            // Stage h[64][kb..kb+256)
#pragma unroll
            for (int i = 0; i < 16; i++) {
                int v = i * 256 + tid;
                int b = v >> 6;
                int kq = (v & 63) * 4;
                float4 hv = *(const float4*)&hprev[(size_t)b * HH + kb + kq];
                *(float4*)&hs[b * HS_STRIDE + kq] = hv;
            }
            __syncthreads();

            const int kw = w * 32;
#pragma unroll
            for (int c = 0; c < 8; c++) {
                const int kk = kw + c * 4;
                unsigned long long hv2[8][2];
#pragma unroll
                for (int i = 0; i < 8; i++) {
                    float4 v = *(const float4*)&hs[(bg + 8 * i) * HS_STRIDE + kk];
                    hv2[i][0] = *(unsigned long long*)&v.x;
                    hv2[i][1] = *(unsigned long long*)&v.z;
                }
#pragma unroll
                for (int jj = 0; jj < 2; jj++) {
#pragma unroll
                    for (int g = 0; g < 3; g++) {
                        float4 wv = *(const float4*)&ws[(g * 8 + jp * 2 + jj) * WS_STRIDE + kb + kk];
                        unsigned long long w0 = *(unsigned long long*)&wv.x;
                        unsigned long long w1 = *(unsigned long long*)&wv.z;
#pragma unroll
                        for (int i = 0; i < 8; i++) {
                            fma2(acc2[i][jj][g], hv2[i][0], w0);
                            fma2(acc2[i][jj][g], hv2[i][1], w1);
                        }
                    }
                }
            }
        }

        __syncthreads();   // all warps done reading hs; safe to overwrite as red
#pragma unroll
        for (int i = 0; i < 8; i++)
#pragma unroll
            for (int jj = 0; jj < 2; jj++)
#pragma unroll
                for (int g = 0; g < 3; g++) {
                    int jloc = jp * 2 + jj;
                    int b = bg + 8 * i;
                    red[w * 1536 + g * 512 + jloc * 64 + b] = fold2(acc2[i][jj][g]);
                }
        __syncthreads();

        // Gate epilogue: 512 (b,j) outputs, 2 per thread
#pragma unroll
        for (int q = 0; q < 2; q++) {
            int p2 = tid + q * 256;
            int jloc = p2 >> 6;
            int b = p2 & 63;
            int j = jbase + jloc;
            float sr = 0.f, sz = 0.f, sn = 0.f;
#pragma unroll
            for (int ww = 0; ww < 8; ww++) {
                sr += red[ww * 1536 + 0 * 512 + p2];
                sz += red[ww * 1536 + 1 * 512 + p2];
                sn += red[ww * 1536 + 2 * 512 + p2];
            }
            size_t girow = ((size_t)(s * BB + b)) * (3 * HH);
            float ir  = g_gi[girow + j];
            float iz  = g_gi[girow + HH + j];
            float in_ = g_gi[girow + 2 * HH + j];
            float hr = sr + bhh[j];
            float hz = sz + bhh[HH + j];
            float hn = sn + bhh[2 * HH + j];
            float r = 1.f / (1.f + expf(-(ir + hr)));
            float z = 1.f / (1.f + expf(-(iz + hz)));
            float n = tanhf(in_ + r * hn);
            float hold = hprev[(size_t)b * HH + j];
            float hnew = (1.f - z) * n + z * hold;
            g_hist[(size_t)t * BB * HH + (size_t)b * HH + j] = hnew;
        }

        // Device-wide barrier (skip after the final tick)
        if (t < TT - 1) {
            __threadfence();     // make this thread's g_hist stores visible
            __syncthreads();     // all threads of block fenced before arrive
            if (tid == 0) {
                atomicAdd(&g_barr[t], 1u);
                while (atomicAdd(&g_barr[t], 0u) < 128u) { }
                __threadfence();
            }
            __syncthreads();
        }
    }
}

// ---------------------------------------------------------------------------
// K3: logits[b][t][:] = (g_hist[t][b][:] @ W_fc^T + b_fc) * seq_mask[b][t>>2]
// ---------------------------------------------------------------------------
__global__ __launch_bounds__(256) void logits_kernel(const float* __restrict__ Wfc,
                                                     const float* __restrict__ bfc,
                                                     const float* __restrict__ smask,
                                                     float* __restrict__ out)
{
    __shared__ float As[8][128];
    __shared__ float Bs[8][128];
    const int mbase = blockIdx.y * 128;
    const int nbase = blockIdx.x * 128;
    const int tid   = threadIdx.x;
    const int lrow  = tid >> 1;
    const int lkq   = (tid & 1) * 4;
    const int tx    = (tid & 15) * 8;
    const int ty    = (tid >> 4) * 8;

    float acc[8][8];
#pragma unroll
    for (int i = 0; i < 8; i++)
#pragma unroll
        for (int j = 0; j < 8; j++) acc[i][j] = 0.f;

    for (int k0 = 0; k0 < HH; k0 += 8) {
        float4 av = *(const float4*)&g_hist[(size_t)(mbase + lrow) * HH + k0 + lkq];
        float4 bv = *(const float4*)&Wfc[(size_t)(nbase + lrow) * HH + k0 + lkq];
        __syncthreads();
        As[lkq + 0][lrow] = av.x; As[lkq + 1][lrow] = av.y;
        As[lkq + 2][lrow] = av.z; As[lkq + 3][lrow] = av.w;
        Bs[lkq + 0][lrow] = bv.x; Bs[lkq + 1][lrow] = bv.y;
        Bs[lkq + 2][lrow] = bv.z; Bs[lkq + 3][lrow] = bv.w;
        __syncthreads();
#pragma unroll
        for (int kk = 0; kk < 8; kk++) {
            float ar[8], br[8];
#pragma unroll
            for (int i = 0; i < 8; i++) ar[i] = As[kk][ty + i];
#pragma unroll
            for (int j = 0; j < 8; j++) br[j] = Bs[kk][tx + j];
#pragma unroll
            for (int i = 0; i < 8; i++)
#pragma unroll
                for (int j = 0; j < 8; j++) acc[i][j] += ar[i] * br[j];
        }
    }

#pragma unroll
    for (int i = 0; i < 8; i++) {
        int m = mbase + ty + i;
        int t = m >> 6;          // m = t*64 + b
        int b = m & 63;
        int s = t >> 2;
        float mk = smask[b * SS + s];
        size_t obase = ((size_t)b * TT + t) * OO;
#pragma unroll
        for (int j = 0; j < 8; j++) {
            int n = nbase + tx + j;
            out[obase + n] = (acc[i][j] + bfc[n]) * mk;
        }
    }
}

// ---------------------------------------------------------------------------
// K4: y_res (repeated labels) and ok (mask!=0) appended after logits.
// ---------------------------------------------------------------------------
__global__ void tail_kernel(const int* __restrict__ y,
                            const float* __restrict__ smask,
                            float* __restrict__ out)
{
    int idx = blockIdx.x * blockDim.x + threadIdx.x;
    if (idx < BB * TT) {
        int b = idx >> 10;
        int t = idx & 1023;
        int s = t >> 2;
        size_t base1 = (size_t)BB * TT * OO;
        out[base1 + idx] = (float)y[b * SS + s];
        out[base1 + (size_t)BB * TT + idx] = (smask[b * SS + s] != 0.f) ? 1.f : 0.f;
    }
}

// ---------------------------------------------------------------------------
extern "C" void kernel_launch(void* const* d_in, const int* in_sizes, int n_in,
                              void* d_out, int out_size)
{
    const float* x     = (const float*)d_in[0];
    const int*   y     = (const int*)d_in[1];
    const float* smask = (const float*)d_in[2];
    int wi = 3;
    if (n_in >= 10 && in_sizes[3] == 1) wi = 4;  // skip forced_num_ticks scalar
    const float* Wih = (const float*)d_in[wi + 0];
    const float* Whh = (const float*)d_in[wi + 1];
    const float* bih = (const float*)d_in[wi + 2];
    const float* bhh = (const float*)d_in[wi + 3];
    const float* Wfc = (const float*)d_in[wi + 4];
    const float* bfc = (const float*)d_in[wi + 5];
    float* out = (float*)d_out;

    cudaFuncSetAttribute(rec_kernel,
                         cudaFuncAttributeMaxDynamicSharedMemorySize, REC_SMEM);

    // Reset the grid-barrier slots (memset node; stream-ordered before rec)
    void* barr_ptr = 0;
    cudaGetSymbolAddress(&barr_ptr, g_barr);
    cudaMemsetAsync(barr_ptr, 0, TT * sizeof(unsigned int));

    // K1: precompute all input gates
    dim3 g1(3 * HH / 128, (BB * SS) / 128);
    gi_kernel<<<g1, 256>>>(x, Wih, bih);

    // K2: whole recurrence in ONE persistent kernel
    rec_kernel<<<128, 256, REC_SMEM>>>(Whh, bhh);

    // K3: all logits in one GEMM
    dim3 g3(OO / 128, (TT * BB) / 128);
    logits_kernel<<<g3, 256>>>(Wfc, bfc, smask, out);

    // K4: y_res + ok tail (only if harness expects the full concat)
    if ((size_t)out_size > (size_t)BB * TT * OO)
        tail_kernel<<<(BB * TT + 255) / 256, 256>>>(y, smask, out);
}